// round 7
// baseline (speedup 1.0000x reference)
#include <cuda_runtime.h>
#include <cuda_bf16.h>
#include <cstdint>

#define N_NODES 100000
#define N_EDGES 1600000
#define FEAT 64

#define SCAN_TPB 1024
#define SCAN_PER_THREAD 4
#define SCAN_CHUNK (SCAN_TPB * SCAN_PER_THREAD)                      // 4096
#define SCAN_NBLOCKS ((N_NODES + SCAN_CHUNK - 1) / SCAN_CHUNK)       // 25
#define FLAG_VALID (1 << 30)
#define FLAG_MASK  (FLAG_VALID - 1)

// ---------------- scratch (static device globals: allocation-free) ----------
__device__ float g_H[N_NODES * FEAT];
__device__ float g_A[N_NODES * FEAT];
__device__ float g_dinv[N_NODES];
__device__ int   g_rowstart[N_NODES + 1];
__device__ int   g_cursor[N_NODES];
__device__ int2  g_csr[N_EDGES];        // {src, norm-as-int-bits}
__device__ int   g_zr[N_NODES + 64];    // deg + lookback flags, one memset

// ---------------- GEMM ---------------------------------------------------------

__device__ __forceinline__ void gemm_body(const float* __restrict__ X,
                                          const float* __restrict__ W,
                                          int row0, int tid,
                                          float (*Xs)[64], float (*Ws)[64]) {
    {
        const float4* W4 = (const float4*)W;
        float4* Ws4 = (float4*)Ws;
        #pragma unroll
        for (int i = 0; i < 4; i++) Ws4[tid + 256 * i] = W4[tid + 256 * i];
    }
    {
        float4* Xs4 = (float4*)Xs;
        const float4* X4 = (const float4*)X;
        #pragma unroll
        for (int i = 0; i < 4; i++) {
            int li = tid + 256 * i;
            int grow = row0 + (li >> 4);
            Xs4[li] = (grow < N_NODES) ? X4[(size_t)grow * 16 + (li & 15)]
                                       : make_float4(0.f, 0.f, 0.f, 0.f);
        }
    }
    __syncthreads();

    int tc = tid & 15;
    int tr = tid >> 4;

    float acc[4][4];
    #pragma unroll
    for (int i = 0; i < 4; i++)
        #pragma unroll
        for (int j = 0; j < 4; j++) acc[i][j] = 0.f;

    #pragma unroll 8
    for (int k = 0; k < 64; k++) {
        float4 bq = *(const float4*)&Ws[k][4 * tc];
        float a0 = Xs[4 * tr + 0][k];
        float a1 = Xs[4 * tr + 1][k];
        float a2 = Xs[4 * tr + 2][k];
        float a3 = Xs[4 * tr + 3][k];
        acc[0][0] = fmaf(a0, bq.x, acc[0][0]);
        acc[0][1] = fmaf(a0, bq.y, acc[0][1]);
        acc[0][2] = fmaf(a0, bq.z, acc[0][2]);
        acc[0][3] = fmaf(a0, bq.w, acc[0][3]);
        acc[1][0] = fmaf(a1, bq.x, acc[1][0]);
        acc[1][1] = fmaf(a1, bq.y, acc[1][1]);
        acc[1][2] = fmaf(a1, bq.z, acc[1][2]);
        acc[1][3] = fmaf(a1, bq.w, acc[1][3]);
        acc[2][0] = fmaf(a2, bq.x, acc[2][0]);
        acc[2][1] = fmaf(a2, bq.y, acc[2][1]);
        acc[2][2] = fmaf(a2, bq.z, acc[2][2]);
        acc[2][3] = fmaf(a2, bq.w, acc[2][3]);
        acc[3][0] = fmaf(a3, bq.x, acc[3][0]);
        acc[3][1] = fmaf(a3, bq.y, acc[3][1]);
        acc[3][2] = fmaf(a3, bq.z, acc[3][2]);
        acc[3][3] = fmaf(a3, bq.w, acc[3][3]);
    }

    #pragma unroll
    for (int i = 0; i < 4; i++) {
        int grow = row0 + 4 * tr + i;
        if (grow < N_NODES) {
            float4 o = make_float4(acc[i][0], acc[i][1], acc[i][2], acc[i][3]);
            ((float4*)(g_H + (size_t)grow * FEAT))[tc] = o;
        }
    }
}

// Fused: gemm1 + degree histogram (independent work).
__global__ __launch_bounds__(256) void gemm1_hist_kernel(const float* __restrict__ X,
                                                         const float* __restrict__ W,
                                                         const int* __restrict__ dst,
                                                         int gemmBlocks) {
    __shared__ float Xs[64][64];
    __shared__ float Ws[64][64];
    int bid = blockIdx.x;
    if (bid < gemmBlocks) {
        gemm_body(X, W, bid * 64, threadIdx.x, Xs, Ws);
    } else {
        int e4 = (bid - gemmBlocks) * blockDim.x + threadIdx.x;
        if (e4 < N_EDGES / 4) {
            int4 d = ((const int4*)dst)[e4];
            atomicAdd(&g_zr[d.x], 1);
            atomicAdd(&g_zr[d.y], 1);
            atomicAdd(&g_zr[d.z], 1);
            atomicAdd(&g_zr[d.w], 1);
        }
    }
}

__global__ __launch_bounds__(256) void gemm_kernel(const float* __restrict__ X,
                                                   const float* __restrict__ W) {
    __shared__ float Xs[64][64];
    __shared__ float Ws[64][64];
    gemm_body(X, W, blockIdx.x * 64, threadIdx.x, Xs, Ws);
}

// ---------------- graph preprocessing ---------------------------------------

__global__ void scan_kernel() {
    __shared__ int warp_sums[32];
    __shared__ int prefix_s;
    int tid = threadIdx.x;
    int lane = tid & 31, wid = tid >> 5;
    int b = blockIdx.x;
    int idx0 = b * SCAN_CHUNK + tid * SCAN_PER_THREAD;

    int v[SCAN_PER_THREAD];
    int sum = 0;
    #pragma unroll
    for (int j = 0; j < SCAN_PER_THREAD; j++) {
        int i = idx0 + j;
        v[j] = (i < N_NODES) ? g_zr[i] : 0;
        sum += v[j];
    }
    int x = sum;
    #pragma unroll
    for (int d = 1; d < 32; d <<= 1) {
        int t = __shfl_up_sync(0xFFFFFFFFu, x, d);
        if (lane >= d) x += t;
    }
    if (lane == 31) warp_sums[wid] = x;
    __syncthreads();
    if (wid == 0) {
        int s = warp_sums[lane];
        #pragma unroll
        for (int d = 1; d < 32; d <<= 1) {
            int t = __shfl_up_sync(0xFFFFFFFFu, s, d);
            if (lane >= d) s += t;
        }
        warp_sums[lane] = s;
    }
    __syncthreads();
    int thread_excl = (x - sum) + (wid ? warp_sums[wid - 1] : 0);
    int block_total = warp_sums[31];

    if (tid == 0) {
        int pre = 0;
        if (b > 0) {
            int f;
            do { f = atomicAdd(&g_zr[N_NODES + b - 1], 0); } while (f == 0);
            pre = f & FLAG_MASK;
        }
        __threadfence();
        atomicExch(&g_zr[N_NODES + b], FLAG_VALID | (pre + block_total));
        prefix_s = pre;
        if (b == SCAN_NBLOCKS - 1) g_rowstart[N_NODES] = pre + block_total;
    }
    __syncthreads();
    int run = prefix_s + thread_excl;

    #pragma unroll
    for (int j = 0; j < SCAN_PER_THREAD; j++) {
        int i = idx0 + j;
        if (i < N_NODES) {
            g_rowstart[i] = run;
            g_cursor[i]   = run;
            g_dinv[i] = rsqrtf((float)v[j] + 1.0f);
        }
        run += v[j];
    }
}

__global__ void csr_build_kernel(const int* __restrict__ src,
                                 const int* __restrict__ dst) {
    int e4 = blockIdx.x * blockDim.x + threadIdx.x;
    if (e4 < N_EDGES / 4) {
        int4 s = __ldg(&((const int4*)src)[e4]);
        int4 d = __ldg(&((const int4*)dst)[e4]);
        {
            int pos = atomicAdd(&g_cursor[d.x], 1);
            g_csr[pos] = make_int2(s.x, __float_as_int(g_dinv[s.x] * g_dinv[d.x]));
        }
        {
            int pos = atomicAdd(&g_cursor[d.y], 1);
            g_csr[pos] = make_int2(s.y, __float_as_int(g_dinv[s.y] * g_dinv[d.y]));
        }
        {
            int pos = atomicAdd(&g_cursor[d.z], 1);
            g_csr[pos] = make_int2(s.z, __float_as_int(g_dinv[s.z] * g_dinv[d.z]));
        }
        {
            int pos = atomicAdd(&g_cursor[d.w], 1);
            g_csr[pos] = make_int2(s.w, __float_as_int(g_dinv[s.w] * g_dinv[d.w]));
        }
    }
}

// ---------------- aggregation (shuffle-broadcast, idempotent) -----------------
__global__ __launch_bounds__(256) void agg_kernel(const float* __restrict__ b,
                                                  float* __restrict__ out,
                                                  int relu) {
    int lane = threadIdx.x & 31, wid = threadIdx.x >> 5;
    int row = blockIdx.x * 8 + wid;
    if (row >= N_NODES) return;

    int s = g_rowstart[row];
    int e = g_rowstart[row + 1];

    float2 acc = make_float2(0.f, 0.f);
    const float2* H2 = (const float2*)g_H;

    for (int base = s; base < e; base += 32) {
        int idx = base + lane;
        int2 p = (idx < e) ? __ldg(&g_csr[idx]) : make_int2(row, 0);
        int cnt = e - base;
        if (cnt > 32) cnt = 32;
        int lim = (cnt + 7) & ~7;
        #pragma unroll 8
        for (int j = 0; j < lim; j++) {
            int   u  = __shfl_sync(0xFFFFFFFFu, p.x, j);
            float nm = __int_as_float(__shfl_sync(0xFFFFFFFFu, p.y, j));
            float2 v = H2[(size_t)u * 32 + lane];
            acc.x = fmaf(nm, v.x, acc.x);
            acc.y = fmaf(nm, v.y, acc.y);
        }
    }

    float di = g_dinv[row];
    float sw = di * di;
    float2 v  = H2[(size_t)row * 32 + lane];
    float2 bv = ((const float2*)b)[lane];
    acc.x = fmaf(sw, v.x, acc.x) + bv.x;
    acc.y = fmaf(sw, v.y, acc.y) + bv.y;
    if (relu) {
        acc.x = fmaxf(acc.x, 0.f);
        acc.y = fmaxf(acc.y, 0.f);
    }
    ((float2*)(out + (size_t)row * FEAT))[lane] = acc;
}

// ---------------- launch ------------------------------------------------------

extern "C" void kernel_launch(void* const* d_in, const int* in_sizes, int n_in,
                              void* d_out, int out_size) {
    const float* x   = (const float*)d_in[0];
    const int*   ei  = (const int*)d_in[1];
    const float* W1  = (const float*)d_in[2];
    const float* b1  = (const float*)d_in[3];
    const float* W2  = (const float*)d_in[4];
    const float* b2  = (const float*)d_in[5];
    const float* W3  = (const float*)d_in[6];
    const float* b3  = (const float*)d_in[7];
    float* out = (float*)d_out;

    const int* src = ei;
    const int* dst = ei + N_EDGES;

    const int TB = 256;
    const int edge4Blocks = (N_EDGES / 4 + TB - 1) / TB;   // 1563
    const int warpBlocks  = (N_NODES + 7) / 8;             // 12500
    const int gemmBlocks  = (N_NODES + 63) / 64;           // 1563

    void* zr_ptr = nullptr;
    cudaGetSymbolAddress(&zr_ptr, g_zr);
    cudaMemsetAsync(zr_ptr, 0, sizeof(int) * (N_NODES + 64));

    gemm1_hist_kernel<<<gemmBlocks + edge4Blocks, TB>>>(x, W1, dst, gemmBlocks);
    scan_kernel<<<SCAN_NBLOCKS, SCAN_TPB>>>();
    csr_build_kernel<<<edge4Blocks, TB>>>(src, dst);

    // PROBE: agg1 launched twice (pure gather -> idempotent, identical output).
    // Wall-time delta vs R4/R5 baseline == true in-wall cost of one agg launch.
    agg_kernel<<<warpBlocks, TB>>>(b1, g_A, 1);
    agg_kernel<<<warpBlocks, TB>>>(b1, g_A, 1);

    gemm_kernel<<<gemmBlocks, TB>>>(g_A, W2);
    agg_kernel<<<warpBlocks, TB>>>(b2, g_A, 1);

    gemm_kernel<<<gemmBlocks, TB>>>(g_A, W3);
    agg_kernel<<<warpBlocks, TB>>>(b3, out, 0);

    (void)in_sizes; (void)n_in; (void)out_size;
}

// round 8
// speedup vs baseline: 1.2124x; 1.2124x over previous
#include <cuda_runtime.h>
#include <cuda_bf16.h>
#include <cstdint>

#define N_NODES 100000
#define N_EDGES 1600000
#define FEAT 64

#define SCAN_TPB 1024
#define SCAN_PER_THREAD 4
#define SCAN_CHUNK (SCAN_TPB * SCAN_PER_THREAD)                      // 4096
#define SCAN_NBLOCKS ((N_NODES + SCAN_CHUNK - 1) / SCAN_CHUNK)       // 25
#define FLAG_VALID (1 << 30)
#define FLAG_MASK  (FLAG_VALID - 1)

// ---------------- scratch (static device globals: allocation-free) ----------
__device__ float g_H[N_NODES * FEAT];
__device__ float g_A[N_NODES * FEAT];
__device__ float g_dinv[N_NODES];
__device__ int   g_rowstart[N_NODES + 1];
__device__ int   g_cursor[N_NODES];
__device__ int2  g_csr[N_EDGES];        // {src, norm-as-int-bits}
__device__ int   g_zr[N_NODES + 64];    // deg + lookback flags, one memset

// ---------------- GEMM ---------------------------------------------------------

__device__ __forceinline__ void gemm_body(const float* __restrict__ X,
                                          const float* __restrict__ W,
                                          int row0, int tid,
                                          float (*Xs)[64], float (*Ws)[64]) {
    {
        const float4* W4 = (const float4*)W;
        float4* Ws4 = (float4*)Ws;
        #pragma unroll
        for (int i = 0; i < 4; i++) Ws4[tid + 256 * i] = W4[tid + 256 * i];
    }
    {
        float4* Xs4 = (float4*)Xs;
        const float4* X4 = (const float4*)X;
        #pragma unroll
        for (int i = 0; i < 4; i++) {
            int li = tid + 256 * i;
            int grow = row0 + (li >> 4);
            Xs4[li] = (grow < N_NODES) ? X4[(size_t)grow * 16 + (li & 15)]
                                       : make_float4(0.f, 0.f, 0.f, 0.f);
        }
    }
    __syncthreads();

    int tc = tid & 15;
    int tr = tid >> 4;

    float acc[4][4];
    #pragma unroll
    for (int i = 0; i < 4; i++)
        #pragma unroll
        for (int j = 0; j < 4; j++) acc[i][j] = 0.f;

    #pragma unroll 8
    for (int k = 0; k < 64; k++) {
        float4 bq = *(const float4*)&Ws[k][4 * tc];
        float a0 = Xs[4 * tr + 0][k];
        float a1 = Xs[4 * tr + 1][k];
        float a2 = Xs[4 * tr + 2][k];
        float a3 = Xs[4 * tr + 3][k];
        acc[0][0] = fmaf(a0, bq.x, acc[0][0]);
        acc[0][1] = fmaf(a0, bq.y, acc[0][1]);
        acc[0][2] = fmaf(a0, bq.z, acc[0][2]);
        acc[0][3] = fmaf(a0, bq.w, acc[0][3]);
        acc[1][0] = fmaf(a1, bq.x, acc[1][0]);
        acc[1][1] = fmaf(a1, bq.y, acc[1][1]);
        acc[1][2] = fmaf(a1, bq.z, acc[1][2]);
        acc[1][3] = fmaf(a1, bq.w, acc[1][3]);
        acc[2][0] = fmaf(a2, bq.x, acc[2][0]);
        acc[2][1] = fmaf(a2, bq.y, acc[2][1]);
        acc[2][2] = fmaf(a2, bq.z, acc[2][2]);
        acc[2][3] = fmaf(a2, bq.w, acc[2][3]);
        acc[3][0] = fmaf(a3, bq.x, acc[3][0]);
        acc[3][1] = fmaf(a3, bq.y, acc[3][1]);
        acc[3][2] = fmaf(a3, bq.z, acc[3][2]);
        acc[3][3] = fmaf(a3, bq.w, acc[3][3]);
    }

    #pragma unroll
    for (int i = 0; i < 4; i++) {
        int grow = row0 + 4 * tr + i;
        if (grow < N_NODES) {
            float4 o = make_float4(acc[i][0], acc[i][1], acc[i][2], acc[i][3]);
            ((float4*)(g_H + (size_t)grow * FEAT))[tc] = o;
        }
    }
}

// Fused: gemm1 + degree histogram (independent work).
__global__ __launch_bounds__(256) void gemm1_hist_kernel(const float* __restrict__ X,
                                                         const float* __restrict__ W,
                                                         const int* __restrict__ dst,
                                                         int gemmBlocks) {
    __shared__ float Xs[64][64];
    __shared__ float Ws[64][64];
    int bid = blockIdx.x;
    if (bid < gemmBlocks) {
        gemm_body(X, W, bid * 64, threadIdx.x, Xs, Ws);
    } else {
        int e4 = (bid - gemmBlocks) * blockDim.x + threadIdx.x;
        if (e4 < N_EDGES / 4) {
            int4 d = ((const int4*)dst)[e4];
            atomicAdd(&g_zr[d.x], 1);
            atomicAdd(&g_zr[d.y], 1);
            atomicAdd(&g_zr[d.z], 1);
            atomicAdd(&g_zr[d.w], 1);
        }
    }
}

__global__ __launch_bounds__(256) void gemm_kernel(const float* __restrict__ X,
                                                   const float* __restrict__ W) {
    __shared__ float Xs[64][64];
    __shared__ float Ws[64][64];
    gemm_body(X, W, blockIdx.x * 64, threadIdx.x, Xs, Ws);
}

// ---------------- graph preprocessing ---------------------------------------

__global__ void scan_kernel() {
    __shared__ int warp_sums[32];
    __shared__ int prefix_s;
    int tid = threadIdx.x;
    int lane = tid & 31, wid = tid >> 5;
    int b = blockIdx.x;
    int idx0 = b * SCAN_CHUNK + tid * SCAN_PER_THREAD;

    int v[SCAN_PER_THREAD];
    int sum = 0;
    #pragma unroll
    for (int j = 0; j < SCAN_PER_THREAD; j++) {
        int i = idx0 + j;
        v[j] = (i < N_NODES) ? g_zr[i] : 0;
        sum += v[j];
    }
    int x = sum;
    #pragma unroll
    for (int d = 1; d < 32; d <<= 1) {
        int t = __shfl_up_sync(0xFFFFFFFFu, x, d);
        if (lane >= d) x += t;
    }
    if (lane == 31) warp_sums[wid] = x;
    __syncthreads();
    if (wid == 0) {
        int s = warp_sums[lane];
        #pragma unroll
        for (int d = 1; d < 32; d <<= 1) {
            int t = __shfl_up_sync(0xFFFFFFFFu, s, d);
            if (lane >= d) s += t;
        }
        warp_sums[lane] = s;
    }
    __syncthreads();
    int thread_excl = (x - sum) + (wid ? warp_sums[wid - 1] : 0);
    int block_total = warp_sums[31];

    if (tid == 0) {
        int pre = 0;
        if (b > 0) {
            int f;
            do { f = atomicAdd(&g_zr[N_NODES + b - 1], 0); } while (f == 0);
            pre = f & FLAG_MASK;
        }
        __threadfence();
        atomicExch(&g_zr[N_NODES + b], FLAG_VALID | (pre + block_total));
        prefix_s = pre;
        if (b == SCAN_NBLOCKS - 1) g_rowstart[N_NODES] = pre + block_total;
    }
    __syncthreads();
    int run = prefix_s + thread_excl;

    #pragma unroll
    for (int j = 0; j < SCAN_PER_THREAD; j++) {
        int i = idx0 + j;
        if (i < N_NODES) {
            g_rowstart[i] = run;
            g_cursor[i]   = run;
            g_dinv[i] = rsqrtf((float)v[j] + 1.0f);
        }
        run += v[j];
    }
}

__global__ void csr_build_kernel(const int* __restrict__ src,
                                 const int* __restrict__ dst) {
    int e4 = blockIdx.x * blockDim.x + threadIdx.x;
    if (e4 < N_EDGES / 4) {
        int4 s = __ldg(&((const int4*)src)[e4]);
        int4 d = __ldg(&((const int4*)dst)[e4]);
        {
            int pos = atomicAdd(&g_cursor[d.x], 1);
            g_csr[pos] = make_int2(s.x, __float_as_int(g_dinv[s.x] * g_dinv[d.x]));
        }
        {
            int pos = atomicAdd(&g_cursor[d.y], 1);
            g_csr[pos] = make_int2(s.y, __float_as_int(g_dinv[s.y] * g_dinv[d.y]));
        }
        {
            int pos = atomicAdd(&g_cursor[d.z], 1);
            g_csr[pos] = make_int2(s.z, __float_as_int(g_dinv[s.z] * g_dinv[d.z]));
        }
        {
            int pos = atomicAdd(&g_cursor[d.w], 1);
            g_csr[pos] = make_int2(s.w, __float_as_int(g_dinv[s.w] * g_dinv[d.w]));
        }
    }
}

// ---------------- aggregation --------------------------------------------------
// Warp per dst row; 32 edges per coalesced csr load; inner loop in groups of 8:
// 8 shuffles -> 8 INDEPENDENT float2 gathers -> 8 FMAs.
// __launch_bounds__(256, 4) lifts the reg cap to 64 so ptxas can keep all 8
// gathers in flight (previous builds were reg-capped at 32 -> MLP 1-2).
__global__ __launch_bounds__(256, 4) void agg_kernel(const float* __restrict__ b,
                                                     float* __restrict__ out,
                                                     int relu) {
    int lane = threadIdx.x & 31, wid = threadIdx.x >> 5;
    int row = blockIdx.x * 8 + wid;
    if (row >= N_NODES) return;

    int s = g_rowstart[row];
    int e = g_rowstart[row + 1];

    float2 acc = make_float2(0.f, 0.f);
    const float2* H2 = (const float2*)g_H;

    for (int base = s; base < e; base += 32) {
        int idx = base + lane;
        int2 p = (idx < e) ? __ldg(&g_csr[idx]) : make_int2(row, 0);
        int cnt = e - base;
        if (cnt > 32) cnt = 32;
        for (int g0 = 0; g0 < cnt; g0 += 8) {
            int   u[8];
            float nm[8];
            #pragma unroll
            for (int j = 0; j < 8; j++) {
                u[j]  = __shfl_sync(0xFFFFFFFFu, p.x, g0 + j);
                nm[j] = __int_as_float(__shfl_sync(0xFFFFFFFFu, p.y, g0 + j));
            }
            float2 v[8];
            #pragma unroll
            for (int j = 0; j < 8; j++)
                v[j] = H2[(size_t)u[j] * 32 + lane];
            #pragma unroll
            for (int j = 0; j < 8; j++) {
                acc.x = fmaf(nm[j], v[j].x, acc.x);
                acc.y = fmaf(nm[j], v[j].y, acc.y);
            }
        }
    }

    float di = g_dinv[row];
    float sw = di * di;
    float2 v  = H2[(size_t)row * 32 + lane];
    float2 bv = ((const float2*)b)[lane];
    acc.x = fmaf(sw, v.x, acc.x) + bv.x;
    acc.y = fmaf(sw, v.y, acc.y) + bv.y;
    if (relu) {
        acc.x = fmaxf(acc.x, 0.f);
        acc.y = fmaxf(acc.y, 0.f);
    }
    ((float2*)(out + (size_t)row * FEAT))[lane] = acc;
}

// ---------------- launch ------------------------------------------------------

extern "C" void kernel_launch(void* const* d_in, const int* in_sizes, int n_in,
                              void* d_out, int out_size) {
    const float* x   = (const float*)d_in[0];
    const int*   ei  = (const int*)d_in[1];
    const float* W1  = (const float*)d_in[2];
    const float* b1  = (const float*)d_in[3];
    const float* W2  = (const float*)d_in[4];
    const float* b2  = (const float*)d_in[5];
    const float* W3  = (const float*)d_in[6];
    const float* b3  = (const float*)d_in[7];
    float* out = (float*)d_out;

    const int* src = ei;
    const int* dst = ei + N_EDGES;

    const int TB = 256;
    const int edge4Blocks = (N_EDGES / 4 + TB - 1) / TB;   // 1563
    const int warpBlocks  = (N_NODES + 7) / 8;             // 12500
    const int gemmBlocks  = (N_NODES + 63) / 64;           // 1563

    void* zr_ptr = nullptr;
    cudaGetSymbolAddress(&zr_ptr, g_zr);
    cudaMemsetAsync(zr_ptr, 0, sizeof(int) * (N_NODES + 64));

    gemm1_hist_kernel<<<gemmBlocks + edge4Blocks, TB>>>(x, W1, dst, gemmBlocks);
    scan_kernel<<<SCAN_NBLOCKS, SCAN_TPB>>>();
    csr_build_kernel<<<edge4Blocks, TB>>>(src, dst);

    agg_kernel<<<warpBlocks, TB>>>(b1, g_A, 1);

    gemm_kernel<<<gemmBlocks, TB>>>(g_A, W2);
    agg_kernel<<<warpBlocks, TB>>>(b2, g_A, 1);

    gemm_kernel<<<gemmBlocks, TB>>>(g_A, W3);
    agg_kernel<<<warpBlocks, TB>>>(b3, out, 0);

    (void)in_sizes; (void)n_in; (void)out_size;
}

// round 9
// speedup vs baseline: 1.2187x; 1.0052x over previous
#include <cuda_runtime.h>
#include <cuda_fp16.h>
#include <cstdint>

#define N_NODES 100000
#define N_EDGES 1600000
#define FEAT 64

#define SCAN_TPB 1024
#define SCAN_PER_THREAD 4
#define SCAN_CHUNK (SCAN_TPB * SCAN_PER_THREAD)                      // 4096
#define SCAN_NBLOCKS ((N_NODES + SCAN_CHUNK - 1) / SCAN_CHUNK)       // 25
#define FLAG_VALID (1 << 30)
#define FLAG_MASK  (FLAG_VALID - 1)

// ---------------- scratch (static device globals: allocation-free) ----------
__device__ __half g_H[N_NODES * FEAT];  // transformed features, fp16 STORAGE
__device__ float  g_A[N_NODES * FEAT];  // activations stay fp32
__device__ float  g_dinv[N_NODES];
__device__ int    g_rowstart[N_NODES + 1];
__device__ int    g_cursor[N_NODES];
__device__ int2   g_csr[N_EDGES];       // {src, norm-as-int-bits}
__device__ int    g_zr[N_NODES + 64];   // deg + lookback flags, one memset

// ---------------- GEMM (fp32 compute, fp16 H output) -------------------------

__device__ __forceinline__ void gemm_body(const float* __restrict__ X,
                                          const float* __restrict__ W,
                                          int row0, int tid,
                                          float (*Xs)[64], float (*Ws)[64]) {
    {
        const float4* W4 = (const float4*)W;
        float4* Ws4 = (float4*)Ws;
        #pragma unroll
        for (int i = 0; i < 4; i++) Ws4[tid + 256 * i] = W4[tid + 256 * i];
    }
    {
        float4* Xs4 = (float4*)Xs;
        const float4* X4 = (const float4*)X;
        #pragma unroll
        for (int i = 0; i < 4; i++) {
            int li = tid + 256 * i;
            int grow = row0 + (li >> 4);
            Xs4[li] = (grow < N_NODES) ? X4[(size_t)grow * 16 + (li & 15)]
                                       : make_float4(0.f, 0.f, 0.f, 0.f);
        }
    }
    __syncthreads();

    int tc = tid & 15;
    int tr = tid >> 4;

    float acc[4][4];
    #pragma unroll
    for (int i = 0; i < 4; i++)
        #pragma unroll
        for (int j = 0; j < 4; j++) acc[i][j] = 0.f;

    #pragma unroll 8
    for (int k = 0; k < 64; k++) {
        float4 bq = *(const float4*)&Ws[k][4 * tc];
        float a0 = Xs[4 * tr + 0][k];
        float a1 = Xs[4 * tr + 1][k];
        float a2 = Xs[4 * tr + 2][k];
        float a3 = Xs[4 * tr + 3][k];
        acc[0][0] = fmaf(a0, bq.x, acc[0][0]);
        acc[0][1] = fmaf(a0, bq.y, acc[0][1]);
        acc[0][2] = fmaf(a0, bq.z, acc[0][2]);
        acc[0][3] = fmaf(a0, bq.w, acc[0][3]);
        acc[1][0] = fmaf(a1, bq.x, acc[1][0]);
        acc[1][1] = fmaf(a1, bq.y, acc[1][1]);
        acc[1][2] = fmaf(a1, bq.z, acc[1][2]);
        acc[1][3] = fmaf(a1, bq.w, acc[1][3]);
        acc[2][0] = fmaf(a2, bq.x, acc[2][0]);
        acc[2][1] = fmaf(a2, bq.y, acc[2][1]);
        acc[2][2] = fmaf(a2, bq.z, acc[2][2]);
        acc[2][3] = fmaf(a2, bq.w, acc[2][3]);
        acc[3][0] = fmaf(a3, bq.x, acc[3][0]);
        acc[3][1] = fmaf(a3, bq.y, acc[3][1]);
        acc[3][2] = fmaf(a3, bq.z, acc[3][2]);
        acc[3][3] = fmaf(a3, bq.w, acc[3][3]);
    }

    // epilogue: convert 4 fp32 -> 2 half2, one 8B store per row-slice
    #pragma unroll
    for (int i = 0; i < 4; i++) {
        int grow = row0 + 4 * tr + i;
        if (grow < N_NODES) {
            __half2 h0 = __floats2half2_rn(acc[i][0], acc[i][1]);
            __half2 h1 = __floats2half2_rn(acc[i][2], acc[i][3]);
            uint2 pk = make_uint2(*(const unsigned*)&h0, *(const unsigned*)&h1);
            ((uint2*)(g_H + (size_t)grow * FEAT))[tc] = pk;
        }
    }
}

// Fused: gemm1 + degree histogram (independent work).
__global__ __launch_bounds__(256) void gemm1_hist_kernel(const float* __restrict__ X,
                                                         const float* __restrict__ W,
                                                         const int* __restrict__ dst,
                                                         int gemmBlocks) {
    __shared__ float Xs[64][64];
    __shared__ float Ws[64][64];
    int bid = blockIdx.x;
    if (bid < gemmBlocks) {
        gemm_body(X, W, bid * 64, threadIdx.x, Xs, Ws);
    } else {
        int e4 = (bid - gemmBlocks) * blockDim.x + threadIdx.x;
        if (e4 < N_EDGES / 4) {
            int4 d = ((const int4*)dst)[e4];
            atomicAdd(&g_zr[d.x], 1);
            atomicAdd(&g_zr[d.y], 1);
            atomicAdd(&g_zr[d.z], 1);
            atomicAdd(&g_zr[d.w], 1);
        }
    }
}

__global__ __launch_bounds__(256) void gemm_kernel(const float* __restrict__ X,
                                                   const float* __restrict__ W) {
    __shared__ float Xs[64][64];
    __shared__ float Ws[64][64];
    gemm_body(X, W, blockIdx.x * 64, threadIdx.x, Xs, Ws);
}

// ---------------- graph preprocessing ---------------------------------------

__global__ void scan_kernel() {
    __shared__ int warp_sums[32];
    __shared__ int prefix_s;
    int tid = threadIdx.x;
    int lane = tid & 31, wid = tid >> 5;
    int b = blockIdx.x;
    int idx0 = b * SCAN_CHUNK + tid * SCAN_PER_THREAD;

    int v[SCAN_PER_THREAD];
    int sum = 0;
    #pragma unroll
    for (int j = 0; j < SCAN_PER_THREAD; j++) {
        int i = idx0 + j;
        v[j] = (i < N_NODES) ? g_zr[i] : 0;
        sum += v[j];
    }
    int x = sum;
    #pragma unroll
    for (int d = 1; d < 32; d <<= 1) {
        int t = __shfl_up_sync(0xFFFFFFFFu, x, d);
        if (lane >= d) x += t;
    }
    if (lane == 31) warp_sums[wid] = x;
    __syncthreads();
    if (wid == 0) {
        int s = warp_sums[lane];
        #pragma unroll
        for (int d = 1; d < 32; d <<= 1) {
            int t = __shfl_up_sync(0xFFFFFFFFu, s, d);
            if (lane >= d) s += t;
        }
        warp_sums[lane] = s;
    }
    __syncthreads();
    int thread_excl = (x - sum) + (wid ? warp_sums[wid - 1] : 0);
    int block_total = warp_sums[31];

    if (tid == 0) {
        int pre = 0;
        if (b > 0) {
            int f;
            do { f = atomicAdd(&g_zr[N_NODES + b - 1], 0); } while (f == 0);
            pre = f & FLAG_MASK;
        }
        __threadfence();
        atomicExch(&g_zr[N_NODES + b], FLAG_VALID | (pre + block_total));
        prefix_s = pre;
        if (b == SCAN_NBLOCKS - 1) g_rowstart[N_NODES] = pre + block_total;
    }
    __syncthreads();
    int run = prefix_s + thread_excl;

    #pragma unroll
    for (int j = 0; j < SCAN_PER_THREAD; j++) {
        int i = idx0 + j;
        if (i < N_NODES) {
            g_rowstart[i] = run;
            g_cursor[i]   = run;
            g_dinv[i] = rsqrtf((float)v[j] + 1.0f);
        }
        run += v[j];
    }
}

__global__ void csr_build_kernel(const int* __restrict__ src,
                                 const int* __restrict__ dst) {
    int e4 = blockIdx.x * blockDim.x + threadIdx.x;
    if (e4 < N_EDGES / 4) {
        int4 s = __ldg(&((const int4*)src)[e4]);
        int4 d = __ldg(&((const int4*)dst)[e4]);
        {
            int pos = atomicAdd(&g_cursor[d.x], 1);
            g_csr[pos] = make_int2(s.x, __float_as_int(g_dinv[s.x] * g_dinv[d.x]));
        }
        {
            int pos = atomicAdd(&g_cursor[d.y], 1);
            g_csr[pos] = make_int2(s.y, __float_as_int(g_dinv[s.y] * g_dinv[d.y]));
        }
        {
            int pos = atomicAdd(&g_cursor[d.z], 1);
            g_csr[pos] = make_int2(s.z, __float_as_int(g_dinv[s.z] * g_dinv[d.z]));
        }
        {
            int pos = atomicAdd(&g_cursor[d.w], 1);
            g_csr[pos] = make_int2(s.w, __float_as_int(g_dinv[s.w] * g_dinv[d.w]));
        }
    }
}

// ---------------- aggregation --------------------------------------------------
// Warp per dst row; coalesced csr load covers 32 edges; shuffle-broadcast of
// (src, norm); each lane loads ONE half2 (4B) -> warp gather = 128B = 1 line
// per edge (was 2 lines / 256B in fp32). fp32 accumulate.
__global__ __launch_bounds__(256) void agg_kernel(const float* __restrict__ b,
                                                  float* __restrict__ out,
                                                  int relu) {
    int lane = threadIdx.x & 31, wid = threadIdx.x >> 5;
    int row = blockIdx.x * 8 + wid;
    if (row >= N_NODES) return;

    int s = g_rowstart[row];
    int e = g_rowstart[row + 1];

    float2 acc = make_float2(0.f, 0.f);
    const __half2* H2 = (const __half2*)g_H;

    for (int base = s; base < e; base += 32) {
        int idx = base + lane;
        int2 p = (idx < e) ? __ldg(&g_csr[idx]) : make_int2(row, 0);
        int cnt = e - base;
        if (cnt > 32) cnt = 32;
        for (int g0 = 0; g0 < cnt; g0 += 8) {
            int   u[8];
            float nm[8];
            #pragma unroll
            for (int j = 0; j < 8; j++) {
                u[j]  = __shfl_sync(0xFFFFFFFFu, p.x, g0 + j);
                nm[j] = __int_as_float(__shfl_sync(0xFFFFFFFFu, p.y, g0 + j));
            }
            __half2 v[8];
            #pragma unroll
            for (int j = 0; j < 8; j++)
                v[j] = H2[(size_t)u[j] * 32 + lane];
            #pragma unroll
            for (int j = 0; j < 8; j++) {
                float2 vf = __half22float2(v[j]);
                acc.x = fmaf(nm[j], vf.x, acc.x);
                acc.y = fmaf(nm[j], vf.y, acc.y);
            }
        }
    }

    float di = g_dinv[row];
    float sw = di * di;
    float2 vf = __half22float2(H2[(size_t)row * 32 + lane]);
    float2 bv = ((const float2*)b)[lane];
    acc.x = fmaf(sw, vf.x, acc.x) + bv.x;
    acc.y = fmaf(sw, vf.y, acc.y) + bv.y;
    if (relu) {
        acc.x = fmaxf(acc.x, 0.f);
        acc.y = fmaxf(acc.y, 0.f);
    }
    ((float2*)(out + (size_t)row * FEAT))[lane] = acc;
}

// ---------------- launch ------------------------------------------------------

extern "C" void kernel_launch(void* const* d_in, const int* in_sizes, int n_in,
                              void* d_out, int out_size) {
    const float* x   = (const float*)d_in[0];
    const int*   ei  = (const int*)d_in[1];
    const float* W1  = (const float*)d_in[2];
    const float* b1  = (const float*)d_in[3];
    const float* W2  = (const float*)d_in[4];
    const float* b2  = (const float*)d_in[5];
    const float* W3  = (const float*)d_in[6];
    const float* b3  = (const float*)d_in[7];
    float* out = (float*)d_out;

    const int* src = ei;
    const int* dst = ei + N_EDGES;

    const int TB = 256;
    const int edge4Blocks = (N_EDGES / 4 + TB - 1) / TB;   // 1563
    const int warpBlocks  = (N_NODES + 7) / 8;             // 12500
    const int gemmBlocks  = (N_NODES + 63) / 64;           // 1563

    void* zr_ptr = nullptr;
    cudaGetSymbolAddress(&zr_ptr, g_zr);
    cudaMemsetAsync(zr_ptr, 0, sizeof(int) * (N_NODES + 64));

    gemm1_hist_kernel<<<gemmBlocks + edge4Blocks, TB>>>(x, W1, dst, gemmBlocks);
    scan_kernel<<<SCAN_NBLOCKS, SCAN_TPB>>>();
    csr_build_kernel<<<edge4Blocks, TB>>>(src, dst);

    agg_kernel<<<warpBlocks, TB>>>(b1, g_A, 1);

    gemm_kernel<<<gemmBlocks, TB>>>(g_A, W2);
    agg_kernel<<<warpBlocks, TB>>>(b2, g_A, 1);

    gemm_kernel<<<gemmBlocks, TB>>>(g_A, W3);
    agg_kernel<<<warpBlocks, TB>>>(b3, out, 0);

    (void)in_sizes; (void)n_in; (void)out_size;
}